// round 13
// baseline (speedup 1.0000x reference)
#include <cuda_runtime.h>
#include <cuda_bf16.h>
#include <cstdint>

// LiveNet: y = relu(x @ W1 + b1) @ W2 + b2
// B=1048576, N_IN=64, N_MID=32, N_OUT=16, fp32.
//
// R13: R12 (55.8us wall; body pinned at the ~74% mixed-R/W HBM ceiling
// across 5 configs) with the pipeline cut to 2 stages -> 44KB smem/CTA ->
// 4 CTAs/SM (16 warps, was 12). Per-warp iteration (~2800cy) >> DRAM
// latency, so distance-1 slack is sufficient; the extra warps test whether
// concurrent issue-stream count can lift DRAM% above 74%.
// Math identical to R5-R12 (mma.sync bf16x3 split, rel_err 6.13e-6).

typedef uint32_t u32;
typedef unsigned long long u64;

__device__ __forceinline__ u32 cvt_bf16x2(float hi, float lo) {
    u32 r; asm("cvt.rn.bf16x2.f32 %0, %1, %2;" : "=r"(r) : "f"(hi), "f"(lo)); return r;
}
// split pair (x0=k even -> low bf16, x1=k odd -> high bf16)
__device__ __forceinline__ void split2(float x0, float x1, u32& hi, u32& lo) {
    hi = cvt_bf16x2(x1, x0);
    const float e0 = __uint_as_float(__byte_perm(hi, 0, 0x1044));
    const float e1 = __uint_as_float(__byte_perm(hi, 0, 0x3244));
    lo = cvt_bf16x2(x1 - e1, x0 - e0);
}
__device__ __forceinline__ void mma_bf16(float& d0, float& d1, float& d2, float& d3,
                                         u32 a0, u32 a1, u32 a2, u32 a3,
                                         u32 b0, u32 b1) {
    asm("mma.sync.aligned.m16n8k16.row.col.f32.bf16.bf16.f32 "
        "{%0,%1,%2,%3}, {%4,%5,%6,%7}, {%8,%9}, {%0,%1,%2,%3};"
        : "+f"(d0), "+f"(d1), "+f"(d2), "+f"(d3)
        : "r"(a0), "r"(a1), "r"(a2), "r"(a3), "r"(b0), "r"(b1));
}
__device__ __forceinline__ void cp16(u32 smem, const void* gmem) {
    asm volatile("cp.async.cg.shared.global.L2::256B [%0], [%1], 16;"
                 :: "r"(smem), "l"(gmem));
}
__device__ __forceinline__ void cp_commit() {
    asm volatile("cp.async.commit_group;" ::: "memory");
}
__device__ __forceinline__ void cp_wait1() {
    asm volatile("cp.async.wait_group 1;" ::: "memory");
}
__device__ __forceinline__ void lds64(u32 addr, float& a, float& b) {
    asm volatile("ld.shared.v2.f32 {%0, %1}, [%2];" : "=f"(a), "=f"(b) : "r"(addr));
}
__device__ __forceinline__ void stg_cs4(float* p, float a, float b, float c, float d) {
    asm volatile("st.global.cs.v4.f32 [%0], {%1, %2, %3, %4};"
                 :: "l"(p), "f"(a), "f"(b), "f"(c), "f"(d));
}
__device__ __forceinline__ u64 pack2f(float lo, float hi) {
    u64 d; asm("mov.b64 %0, {%1, %2};" : "=l"(d) : "f"(lo), "f"(hi)); return d;
}
__device__ __forceinline__ void unpack2f(u64 v, float& lo, float& hi) {
    asm("mov.b64 {%0, %1}, %2;" : "=f"(lo), "=f"(hi) : "l"(v));
}

#define STAGE_BYTES 4096
#define NSTAGES 2
#define CTA_WARPS 4

__global__ __launch_bounds__(CTA_WARPS * 32, 4)
void livenet_mma(const float* __restrict__ x,
                 const float* __restrict__ W1,
                 const float* __restrict__ b1,
                 const float* __restrict__ W2,
                 const float* __restrict__ b2,
                 float* __restrict__ y,
                 int nTiles) {
    extern __shared__ char xstage[];            // 4 warps * 2 stages * 4KB = 32KB

    __shared__ uint2  sB1h[4][4][32];           // [ntile][kstep][lane] GEMM1 W hi
    __shared__ uint2  sB1l[4][4][32];
    __shared__ uint2  sB2h[2][2][32];           // GEMM2 W hi/lo
    __shared__ uint2  sB2l[2][2][32];
    __shared__ float2 sb1[4][32];               // bias fragments (C pairs)
    __shared__ float2 sb2[2][32];

    const int tid  = threadIdx.x;
    const int wid  = tid >> 5;
    const int lane = tid & 31;
    const int g = lane >> 2;     // fragment group row
    const int t = lane & 3;      // thread-in-group

    const int nWarps = gridDim.x * CTA_WARPS;
    const int gw     = blockIdx.x * CTA_WARPS + wid;

    // per-warp stage ring base (smem address space)
    u32 wbase;
    {
        char* p = xstage + wid * (NSTAGES * STAGE_BYTES);
        asm("{ .reg .u64 q; cvta.to.shared.u64 q, %1; cvt.u32.u64 %0, q; }"
            : "=r"(wbase) : "l"(p));
    }

    // cp.async dst offsets: chunk c = lane + 32i, row r = (lane>>4)+2i,
    //   cc = lane&15; dst = r*256 + ((cc*16) ^ ((r&3)<<5))
    const int  rl   = lane >> 4;                                     // 0 or 1
    const u32  swzE = (u32)(((lane & 15) * 16) ^ (rl << 5));         // i even
    const u32  swzO = (u32)(((lane & 15) * 16) ^ ((rl + 2) << 5));   // i odd

    // ---- prologue stage fills FIRST (hide behind weight build) ----
    #pragma unroll
    for (int p = 0; p < NSTAGES; p++) {
        const int pt = gw + p * nWarps;
        if (pt < nTiles) {
            const float4* src = (const float4*)(x + (size_t)pt * 1024) + lane;
            const u32 sb = wbase + (u32)p * STAGE_BYTES;
            #pragma unroll
            for (int i = 0; i < 8; i++)
                cp16(sb + (u32)(((rl + 2 * i) * 256)) + ((i & 1) ? swzO : swzE), src + 32 * i);
        }
        cp_commit();
    }

    // ---- weight fragment build, parallel over warps ----
    {
        const int n = wid;                      // warp wid builds GEMM1 ntile wid
        #pragma unroll
        for (int s = 0; s < 4; s++) {
            const int col = 8 * n + g;
            const float w00 = W1[(16 * s + 2 * t)     * 32 + col];
            const float w01 = W1[(16 * s + 2 * t + 1) * 32 + col];
            const float w10 = W1[(16 * s + 2 * t + 8) * 32 + col];
            const float w11 = W1[(16 * s + 2 * t + 9) * 32 + col];
            u32 h0, l0, h1, l1;
            split2(w00, w01, h0, l0);
            split2(w10, w11, h1, l1);
            sB1h[n][s][lane] = make_uint2(h0, h1);
            sB1l[n][s][lane] = make_uint2(l0, l1);
        }
        sb1[n][lane] = make_float2(b1[8 * n + 2 * t], b1[8 * n + 2 * t + 1]);
    }
    if (wid < 2) {
        const int n = wid;                      // warps 0,1 build GEMM2
        #pragma unroll
        for (int k = 0; k < 2; k++) {
            const int col = 8 * n + g;
            const float w00 = W2[(16 * k + 2 * t)     * 16 + col];
            const float w01 = W2[(16 * k + 2 * t + 1) * 16 + col];
            const float w10 = W2[(16 * k + 2 * t + 8) * 16 + col];
            const float w11 = W2[(16 * k + 2 * t + 9) * 16 + col];
            u32 h0, l0, h1, l1;
            split2(w00, w01, h0, l0);
            split2(w10, w11, h1, l1);
            sB2h[n][k][lane] = make_uint2(h0, h1);
            sB2l[n][k][lane] = make_uint2(l0, l1);
        }
        sb2[n][lane] = make_float2(b2[8 * n + 2 * t], b2[8 * n + 2 * t + 1]);
    }
    __syncthreads();

    if (gw >= nTiles) return;

    // LDS read bases: lane (g,t), row g (+8), byte 8t + 32(u ^ (g&3))
    const u32 roff  = (u32)(g * 256 + 8 * t);
    const u32 rmask = (u32)((g & 3) << 5);
    const int todd  = t & 1;

    int stage = 0;
    for (int tile = gw; tile < nTiles; tile += nWarps) {
        cp_wait1();
        __syncwarp();

        const u32 sb = wbase + (u32)stage * STAGE_BYTES;

        // ---- read x fragments from swizzled smem + hi/lo split ----
        u32 hiA[4][4], loA[4][4];
        #pragma unroll
        for (int s = 0; s < 4; s++) {
            float a0x, a0y, a1x, a1y, a2x, a2y, a3x, a3y;
            const u32 u0 = (u32)(((2 * s) << 5) ^ rmask);
            const u32 u1 = (u32)(((2 * s + 1) << 5) ^ rmask);
            lds64(sb + roff + u0,        a0x, a0y);   // row g,   k=8(2s)+2t
            lds64(sb + roff + u0 + 2048, a1x, a1y);   // row g+8
            lds64(sb + roff + u1,        a2x, a2y);   // row g,   k=8(2s+1)+2t
            lds64(sb + roff + u1 + 2048, a3x, a3y);   // row g+8
            split2(a0x, a0y, hiA[s][0], loA[s][0]);
            split2(a1x, a1y, hiA[s][1], loA[s][1]);
            split2(a2x, a2y, hiA[s][2], loA[s][2]);
            split2(a3x, a3y, hiA[s][3], loA[s][3]);
        }
        __syncwarp();   // all lanes done reading stage before refill

        // ---- refill this stage with tile+2*nWarps (skip cp16s past end) ----
        {
            const int pt = tile + NSTAGES * nWarps;
            if (pt < nTiles) {
                const float4* src = (const float4*)(x + (size_t)pt * 1024) + lane;
                #pragma unroll
                for (int i = 0; i < 8; i++)
                    cp16(sb + (u32)(((rl + 2 * i) * 256)) + ((i & 1) ? swzO : swzE), src + 32 * i);
            }
            cp_commit();
        }

        // ---- GEMM1: D1[n] = x @ W1[:,8n:8n+8] + b1, 3-term split ----
        float D1[4][4];
        #pragma unroll
        for (int n = 0; n < 4; n++) {
            const float2 c = sb1[n][lane];
            float d0 = c.x, d1 = c.y, d2 = c.x, d3 = c.y;
            #pragma unroll
            for (int s = 0; s < 4; s++) {
                const uint2 b = sB1h[n][s][lane];
                mma_bf16(d0, d1, d2, d3, hiA[s][0], hiA[s][1], hiA[s][2], hiA[s][3], b.x, b.y);
            }
            #pragma unroll
            for (int s = 0; s < 4; s++) {
                const uint2 b = sB1l[n][s][lane];
                mma_bf16(d0, d1, d2, d3, hiA[s][0], hiA[s][1], hiA[s][2], hiA[s][3], b.x, b.y);
            }
            #pragma unroll
            for (int s = 0; s < 4; s++) {
                const uint2 b = sB1h[n][s][lane];
                mma_bf16(d0, d1, d2, d3, loA[s][0], loA[s][1], loA[s][2], loA[s][3], b.x, b.y);
            }
            D1[n][0] = fmaxf(d0, 0.0f);
            D1[n][1] = fmaxf(d1, 0.0f);
            D1[n][2] = fmaxf(d2, 0.0f);
            D1[n][3] = fmaxf(d3, 0.0f);
        }

        // ---- h fragments: GEMM1 D layout == GEMM2 A layout ----
        u32 hiH[2][4], loH[2][4];
        #pragma unroll
        for (int k = 0; k < 2; k++) {
            split2(D1[2 * k][0],     D1[2 * k][1],     hiH[k][0], loH[k][0]);
            split2(D1[2 * k][2],     D1[2 * k][3],     hiH[k][1], loH[k][1]);
            split2(D1[2 * k + 1][0], D1[2 * k + 1][1], hiH[k][2], loH[k][2]);
            split2(D1[2 * k + 1][2], D1[2 * k + 1][3], hiH[k][3], loH[k][3]);
        }

        // ---- GEMM2 + paired v4 streaming store ----
        float* yb = y + (size_t)tile * 256;
        #pragma unroll
        for (int n = 0; n < 2; n++) {
            const float2 c = sb2[n][lane];
            float d0 = c.x, d1 = c.y, d2 = c.x, d3 = c.y;
            #pragma unroll
            for (int k = 0; k < 2; k++) {
                const uint2 b = sB2h[n][k][lane];
                mma_bf16(d0, d1, d2, d3, hiH[k][0], hiH[k][1], hiH[k][2], hiH[k][3], b.x, b.y);
            }
            #pragma unroll
            for (int k = 0; k < 2; k++) {
                const uint2 b = sB2l[n][k][lane];
                mma_bf16(d0, d1, d2, d3, hiH[k][0], hiH[k][1], hiH[k][2], hiH[k][3], b.x, b.y);
            }
            #pragma unroll
            for (int k = 0; k < 2; k++) {
                const uint2 b = sB2h[n][k][lane];
                mma_bf16(d0, d1, d2, d3, loH[k][0], loH[k][1], loH[k][2], loH[k][3], b.x, b.y);
            }
            // exchange: even lanes send (d2,d3), odd lanes send (d0,d1)
            const u64 val  = todd ? pack2f(d0, d1) : pack2f(d2, d3);
            const u64 recv = __shfl_xor_sync(0xffffffffu, val, 1);
            float rx, ry;
            unpack2f(recv, rx, ry);
            if (todd)
                stg_cs4(yb + (size_t)(g + 8) * 16 + 8 * n + 2 * t - 2, rx, ry, d2, d3);
            else
                stg_cs4(yb + (size_t)g * 16 + 8 * n + 2 * t, d0, d1, rx, ry);
        }

        stage ^= 1;
    }
}

extern "C" void kernel_launch(void* const* d_in, const int* in_sizes, int n_in,
                              void* d_out, int out_size) {
    const float* x  = (const float*)d_in[0];
    const float* W1 = (const float*)d_in[1];
    const float* b1 = (const float*)d_in[2];
    const float* W2 = (const float*)d_in[3];
    const float* b2 = (const float*)d_in[4];
    float* y = (float*)d_out;

    const int B = in_sizes[0] / 64;
    const int nTiles = B / 16;              // 65536

    const int dynSmem = CTA_WARPS * NSTAGES * STAGE_BYTES;   // 32KB

    static int configured = 0;
    if (!configured) {
        cudaFuncSetAttribute(livenet_mma,
                             cudaFuncAttributeMaxDynamicSharedMemorySize, dynSmem);
        cudaFuncSetAttribute(livenet_mma,
                             cudaFuncAttributePreferredSharedMemoryCarveout, 100);
        configured = 1;
    }

    // 128-thread blocks, 4 blocks/SM (44KB smem each) = 16 warps/SM.
    const int blocks = 608;                 // 152 * 4
    livenet_mma<<<blocks, CTA_WARPS * 32, dynSmem>>>(x, W1, b1, W2, b2, y, nTiles);
}

// round 14
// speedup vs baseline: 1.0293x; 1.0293x over previous
#include <cuda_runtime.h>
#include <cuda_bf16.h>
#include <cstdint>

// LiveNet: y = relu(x @ W1 + b1) @ W2 + b2
// B=1048576, N_IN=64, N_MID=32, N_OUT=16, fp32.
//
// FINAL (R14 = R12, best wall 55.8us): warp-level mma.sync bf16x3 split
// (AhBh+AhBl+AlBh, fp32 accum; rel_err 6.1e-6), per-warp cp.async 3-stage
// smem ring with 32B-XOR swizzle (bank-conflict-free LDS.64), prologue
// fills overlapped with parallel weight-fragment build, GEMM1 D fragment
// reused directly as GEMM2 A fragment, shuffle-paired st.global.cs.v4
// stores. Body measured at ~53us = ~6TB/s = the mixed-R/W HBM ceiling;
// R9/R13 (more warps/stages) and R7 (reg caps) all regressed on wall.

typedef uint32_t u32;
typedef unsigned long long u64;

__device__ __forceinline__ u32 cvt_bf16x2(float hi, float lo) {
    u32 r; asm("cvt.rn.bf16x2.f32 %0, %1, %2;" : "=r"(r) : "f"(hi), "f"(lo)); return r;
}
// split pair (x0=k even -> low bf16, x1=k odd -> high bf16)
__device__ __forceinline__ void split2(float x0, float x1, u32& hi, u32& lo) {
    hi = cvt_bf16x2(x1, x0);
    const float e0 = __uint_as_float(__byte_perm(hi, 0, 0x1044));
    const float e1 = __uint_as_float(__byte_perm(hi, 0, 0x3244));
    lo = cvt_bf16x2(x1 - e1, x0 - e0);
}
__device__ __forceinline__ void mma_bf16(float& d0, float& d1, float& d2, float& d3,
                                         u32 a0, u32 a1, u32 a2, u32 a3,
                                         u32 b0, u32 b1) {
    asm("mma.sync.aligned.m16n8k16.row.col.f32.bf16.bf16.f32 "
        "{%0,%1,%2,%3}, {%4,%5,%6,%7}, {%8,%9}, {%0,%1,%2,%3};"
        : "+f"(d0), "+f"(d1), "+f"(d2), "+f"(d3)
        : "r"(a0), "r"(a1), "r"(a2), "r"(a3), "r"(b0), "r"(b1));
}
__device__ __forceinline__ void cp16(u32 smem, const void* gmem) {
    asm volatile("cp.async.cg.shared.global.L2::256B [%0], [%1], 16;"
                 :: "r"(smem), "l"(gmem));
}
__device__ __forceinline__ void cp_commit() {
    asm volatile("cp.async.commit_group;" ::: "memory");
}
__device__ __forceinline__ void cp_wait2() {
    asm volatile("cp.async.wait_group 2;" ::: "memory");
}
__device__ __forceinline__ void lds64(u32 addr, float& a, float& b) {
    asm volatile("ld.shared.v2.f32 {%0, %1}, [%2];" : "=f"(a), "=f"(b) : "r"(addr));
}
__device__ __forceinline__ void stg_cs4(float* p, float a, float b, float c, float d) {
    asm volatile("st.global.cs.v4.f32 [%0], {%1, %2, %3, %4};"
                 :: "l"(p), "f"(a), "f"(b), "f"(c), "f"(d));
}
__device__ __forceinline__ u64 pack2f(float lo, float hi) {
    u64 d; asm("mov.b64 %0, {%1, %2};" : "=l"(d) : "f"(lo), "f"(hi)); return d;
}
__device__ __forceinline__ void unpack2f(u64 v, float& lo, float& hi) {
    asm("mov.b64 {%0, %1}, %2;" : "=f"(lo), "=f"(hi) : "l"(v));
}

#define STAGE_BYTES 4096
#define NSTAGES 3
#define CTA_WARPS 4

__global__ __launch_bounds__(CTA_WARPS * 32, 3)
void livenet_mma(const float* __restrict__ x,
                 const float* __restrict__ W1,
                 const float* __restrict__ b1,
                 const float* __restrict__ W2,
                 const float* __restrict__ b2,
                 float* __restrict__ y,
                 int nTiles) {
    extern __shared__ char xstage[];            // 4 warps * 3 stages * 4KB = 48KB

    __shared__ uint2  sB1h[4][4][32];           // [ntile][kstep][lane] GEMM1 W hi
    __shared__ uint2  sB1l[4][4][32];
    __shared__ uint2  sB2h[2][2][32];           // GEMM2 W hi/lo
    __shared__ uint2  sB2l[2][2][32];
    __shared__ float2 sb1[4][32];               // bias fragments (C pairs)
    __shared__ float2 sb2[2][32];

    const int tid  = threadIdx.x;
    const int wid  = tid >> 5;
    const int lane = tid & 31;
    const int g = lane >> 2;     // fragment group row
    const int t = lane & 3;      // thread-in-group

    const int nWarps = gridDim.x * CTA_WARPS;
    const int gw     = blockIdx.x * CTA_WARPS + wid;

    // per-warp stage ring base (smem address space)
    u32 wbase;
    {
        char* p = xstage + wid * (NSTAGES * STAGE_BYTES);
        asm("{ .reg .u64 q; cvta.to.shared.u64 q, %1; cvt.u32.u64 %0, q; }"
            : "=r"(wbase) : "l"(p));
    }

    // cp.async dst offsets: chunk c = lane + 32i, row r = (lane>>4)+2i,
    //   cc = lane&15; dst = r*256 + ((cc*16) ^ ((r&3)<<5))
    const int  rl   = lane >> 4;                                     // 0 or 1
    const u32  swzE = (u32)(((lane & 15) * 16) ^ (rl << 5));         // i even
    const u32  swzO = (u32)(((lane & 15) * 16) ^ ((rl + 2) << 5));   // i odd

    // ---- prologue stage fills FIRST (hide behind weight build) ----
    #pragma unroll
    for (int p = 0; p < NSTAGES; p++) {
        const int pt = gw + p * nWarps;
        if (pt < nTiles) {
            const float4* src = (const float4*)(x + (size_t)pt * 1024) + lane;
            const u32 sb = wbase + (u32)p * STAGE_BYTES;
            #pragma unroll
            for (int i = 0; i < 8; i++)
                cp16(sb + (u32)(((rl + 2 * i) * 256)) + ((i & 1) ? swzO : swzE), src + 32 * i);
        }
        cp_commit();
    }

    // ---- weight fragment build, parallel over warps ----
    {
        const int n = wid;                      // warp wid builds GEMM1 ntile wid
        #pragma unroll
        for (int s = 0; s < 4; s++) {
            const int col = 8 * n + g;
            const float w00 = W1[(16 * s + 2 * t)     * 32 + col];
            const float w01 = W1[(16 * s + 2 * t + 1) * 32 + col];
            const float w10 = W1[(16 * s + 2 * t + 8) * 32 + col];
            const float w11 = W1[(16 * s + 2 * t + 9) * 32 + col];
            u32 h0, l0, h1, l1;
            split2(w00, w01, h0, l0);
            split2(w10, w11, h1, l1);
            sB1h[n][s][lane] = make_uint2(h0, h1);
            sB1l[n][s][lane] = make_uint2(l0, l1);
        }
        sb1[n][lane] = make_float2(b1[8 * n + 2 * t], b1[8 * n + 2 * t + 1]);
    }
    if (wid < 2) {
        const int n = wid;                      // warps 0,1 build GEMM2
        #pragma unroll
        for (int k = 0; k < 2; k++) {
            const int col = 8 * n + g;
            const float w00 = W2[(16 * k + 2 * t)     * 16 + col];
            const float w01 = W2[(16 * k + 2 * t + 1) * 16 + col];
            const float w10 = W2[(16 * k + 2 * t + 8) * 16 + col];
            const float w11 = W2[(16 * k + 2 * t + 9) * 16 + col];
            u32 h0, l0, h1, l1;
            split2(w00, w01, h0, l0);
            split2(w10, w11, h1, l1);
            sB2h[n][k][lane] = make_uint2(h0, h1);
            sB2l[n][k][lane] = make_uint2(l0, l1);
        }
        sb2[n][lane] = make_float2(b2[8 * n + 2 * t], b2[8 * n + 2 * t + 1]);
    }
    __syncthreads();

    if (gw >= nTiles) return;

    // LDS read bases: lane (g,t), row g (+8), byte 8t + 32(u ^ (g&3))
    const u32 roff  = (u32)(g * 256 + 8 * t);
    const u32 rmask = (u32)((g & 3) << 5);
    const int todd  = t & 1;

    int stage = 0;
    for (int tile = gw; tile < nTiles; tile += nWarps) {
        cp_wait2();
        __syncwarp();

        const u32 sb = wbase + (u32)stage * STAGE_BYTES;

        // ---- read x fragments from swizzled smem + hi/lo split ----
        u32 hiA[4][4], loA[4][4];
        #pragma unroll
        for (int s = 0; s < 4; s++) {
            float a0x, a0y, a1x, a1y, a2x, a2y, a3x, a3y;
            const u32 u0 = (u32)(((2 * s) << 5) ^ rmask);
            const u32 u1 = (u32)(((2 * s + 1) << 5) ^ rmask);
            lds64(sb + roff + u0,        a0x, a0y);   // row g,   k=8(2s)+2t
            lds64(sb + roff + u0 + 2048, a1x, a1y);   // row g+8
            lds64(sb + roff + u1,        a2x, a2y);   // row g,   k=8(2s+1)+2t
            lds64(sb + roff + u1 + 2048, a3x, a3y);   // row g+8
            split2(a0x, a0y, hiA[s][0], loA[s][0]);
            split2(a1x, a1y, hiA[s][1], loA[s][1]);
            split2(a2x, a2y, hiA[s][2], loA[s][2]);
            split2(a3x, a3y, hiA[s][3], loA[s][3]);
        }
        __syncwarp();   // all lanes done reading stage before refill

        // ---- refill this stage with tile+3*nWarps (skip cp16s past end) ----
        {
            const int pt = tile + NSTAGES * nWarps;
            if (pt < nTiles) {
                const float4* src = (const float4*)(x + (size_t)pt * 1024) + lane;
                #pragma unroll
                for (int i = 0; i < 8; i++)
                    cp16(sb + (u32)(((rl + 2 * i) * 256)) + ((i & 1) ? swzO : swzE), src + 32 * i);
            }
            cp_commit();
        }

        // ---- GEMM1: D1[n] = x @ W1[:,8n:8n+8] + b1, 3-term split ----
        float D1[4][4];
        #pragma unroll
        for (int n = 0; n < 4; n++) {
            const float2 c = sb1[n][lane];
            float d0 = c.x, d1 = c.y, d2 = c.x, d3 = c.y;
            #pragma unroll
            for (int s = 0; s < 4; s++) {
                const uint2 b = sB1h[n][s][lane];
                mma_bf16(d0, d1, d2, d3, hiA[s][0], hiA[s][1], hiA[s][2], hiA[s][3], b.x, b.y);
            }
            #pragma unroll
            for (int s = 0; s < 4; s++) {
                const uint2 b = sB1l[n][s][lane];
                mma_bf16(d0, d1, d2, d3, hiA[s][0], hiA[s][1], hiA[s][2], hiA[s][3], b.x, b.y);
            }
            #pragma unroll
            for (int s = 0; s < 4; s++) {
                const uint2 b = sB1h[n][s][lane];
                mma_bf16(d0, d1, d2, d3, loA[s][0], loA[s][1], loA[s][2], loA[s][3], b.x, b.y);
            }
            D1[n][0] = fmaxf(d0, 0.0f);
            D1[n][1] = fmaxf(d1, 0.0f);
            D1[n][2] = fmaxf(d2, 0.0f);
            D1[n][3] = fmaxf(d3, 0.0f);
        }

        // ---- h fragments: GEMM1 D layout == GEMM2 A layout ----
        u32 hiH[2][4], loH[2][4];
        #pragma unroll
        for (int k = 0; k < 2; k++) {
            split2(D1[2 * k][0],     D1[2 * k][1],     hiH[k][0], loH[k][0]);
            split2(D1[2 * k][2],     D1[2 * k][3],     hiH[k][1], loH[k][1]);
            split2(D1[2 * k + 1][0], D1[2 * k + 1][1], hiH[k][2], loH[k][2]);
            split2(D1[2 * k + 1][2], D1[2 * k + 1][3], hiH[k][3], loH[k][3]);
        }

        // ---- GEMM2 + paired v4 streaming store ----
        // lane-pair (t, t^1) swap halves: even lane stores row g cols
        // [8n+2t .. +3]; odd lane stores row g+8 cols [8n+2t-2 .. +1].
        float* yb = y + (size_t)tile * 256;
        #pragma unroll
        for (int n = 0; n < 2; n++) {
            const float2 c = sb2[n][lane];
            float d0 = c.x, d1 = c.y, d2 = c.x, d3 = c.y;
            #pragma unroll
            for (int k = 0; k < 2; k++) {
                const uint2 b = sB2h[n][k][lane];
                mma_bf16(d0, d1, d2, d3, hiH[k][0], hiH[k][1], hiH[k][2], hiH[k][3], b.x, b.y);
            }
            #pragma unroll
            for (int k = 0; k < 2; k++) {
                const uint2 b = sB2l[n][k][lane];
                mma_bf16(d0, d1, d2, d3, hiH[k][0], hiH[k][1], hiH[k][2], hiH[k][3], b.x, b.y);
            }
            #pragma unroll
            for (int k = 0; k < 2; k++) {
                const uint2 b = sB2h[n][k][lane];
                mma_bf16(d0, d1, d2, d3, loH[k][0], loH[k][1], loH[k][2], loH[k][3], b.x, b.y);
            }
            // exchange: even lanes send (d2,d3), odd lanes send (d0,d1)
            const u64 val  = todd ? pack2f(d0, d1) : pack2f(d2, d3);
            const u64 recv = __shfl_xor_sync(0xffffffffu, val, 1);
            float rx, ry;
            unpack2f(recv, rx, ry);
            if (todd)
                stg_cs4(yb + (size_t)(g + 8) * 16 + 8 * n + 2 * t - 2, rx, ry, d2, d3);
            else
                stg_cs4(yb + (size_t)g * 16 + 8 * n + 2 * t, d0, d1, rx, ry);
        }

        stage = (stage + 1 == NSTAGES) ? 0 : stage + 1;
    }
}

extern "C" void kernel_launch(void* const* d_in, const int* in_sizes, int n_in,
                              void* d_out, int out_size) {
    const float* x  = (const float*)d_in[0];
    const float* W1 = (const float*)d_in[1];
    const float* b1 = (const float*)d_in[2];
    const float* W2 = (const float*)d_in[3];
    const float* b2 = (const float*)d_in[4];
    float* y = (float*)d_out;

    const int B = in_sizes[0] / 64;
    const int nTiles = B / 16;              // 65536

    const int dynSmem = CTA_WARPS * NSTAGES * STAGE_BYTES;   // 48KB

    static int configured = 0;
    if (!configured) {
        cudaFuncSetAttribute(livenet_mma,
                             cudaFuncAttributeMaxDynamicSharedMemorySize, dynSmem);
        cudaFuncSetAttribute(livenet_mma,
                             cudaFuncAttributePreferredSharedMemoryCarveout, 100);
        configured = 1;
    }

    // 128-thread blocks, 3 blocks/SM (60KB smem each) = 12 warps/SM.
    const int blocks = 456;                 // 152 * 3
    livenet_mma<<<blocks, CTA_WARPS * 32, dynSmem>>>(x, W1, b1, W2, b2, y, nTiles);
}